// round 4
// baseline (speedup 1.0000x reference)
#include <cuda_runtime.h>
#include <math.h>

// ---------------------------------------------------------------------------
// EncoderBlock: B=8, N=1024, E=768, H=8, d=96
//   qkvr = x @ w_qkvr + b        [8192, 3072], col = (h*96+dd)*4 + s
//   energy = q @ k^T (UNSCALED); att = softmax(energy) / sqrt(768)
//   out = (att @ v) * r ; reshape -> [8192,768]
//   x1  = LN(out @ w_proj + b_proj + x)
//   y   = LN(gelu(x1 @ w_ff1 + b_ff1) @ w_ff2 + b_ff2 + x1)
// ---------------------------------------------------------------------------

#define Bb    8
#define SEQ   1024
#define EMB   768
#define HEADS 8
#define HD    96
#define MROWS (Bb * SEQ)     // 8192
#define E4    (4 * EMB)      // 3072
#define BH    (Bb * HEADS)   // 64

// Scratch (static device globals; no runtime allocation allowed)
__device__ float g_qkvr  [(size_t)MROWS * E4];
__device__ float g_q     [(size_t)BH * SEQ * HD];
__device__ float g_k     [(size_t)BH * SEQ * HD];
__device__ float g_v     [(size_t)BH * SEQ * HD];
__device__ float g_r     [(size_t)BH * SEQ * HD];
__device__ float g_att   [(size_t)BH * SEQ * SEQ];     // energy, softmaxed in place
__device__ float g_attout[(size_t)MROWS * EMB];
__device__ float g_proj  [(size_t)MROWS * EMB];
__device__ float g_x1    [(size_t)MROWS * EMB];
__device__ float g_ffh   [(size_t)MROWS * E4];
__device__ float g_ff    [(size_t)MROWS * EMB];

// ---------------------------------------------------------------------------
// Generic SGEMM: C[M,N] = A[M,K] @ W[K,N] + bias  (EPI==1: exact GELU)
// 128x128 block tile, BK=16, 256 threads, 8x8 per thread.
// Requires M%128==0, N%128==0, K%16==0 (true for all call sites).
// ---------------------------------------------------------------------------
template <int EPI>
__global__ __launch_bounds__(256) void sgemm_bias(
    const float* __restrict__ A, const float* __restrict__ W,
    const float* __restrict__ bias, float* __restrict__ C,
    int Md, int Nd, int Kd)
{
    __shared__ float As[16][132];   // As[k][m]  (A transposed on load)
    __shared__ float Bs[16][132];   // Bs[k][n]

    const int tid = threadIdx.x;
    const int tx = tid & 15;        // column group
    const int ty = tid >> 4;        // row group
    const int rowStart = blockIdx.y * 128;
    const int colStart = blockIdx.x * 128;

    float acc[8][8];
#pragma unroll
    for (int i = 0; i < 8; i++)
#pragma unroll
        for (int j = 0; j < 8; j++) acc[i][j] = 0.0f;

    for (int kt = 0; kt < Kd; kt += 16) {
        // A tile 128x16 -> As[k][m], two float4 per thread
#pragma unroll
        for (int l = 0; l < 2; l++) {
            int idx = tid + l * 256;           // 0..511
            int row = idx >> 2;                // 0..127
            int k4  = (idx & 3) * 4;           // 0,4,8,12
            float4 va = *(const float4*)&A[(size_t)(rowStart + row) * Kd + kt + k4];
            As[k4 + 0][row] = va.x;
            As[k4 + 1][row] = va.y;
            As[k4 + 2][row] = va.z;
            As[k4 + 3][row] = va.w;
        }
        // W tile 16x128 -> Bs[k][n]
#pragma unroll
        for (int l = 0; l < 2; l++) {
            int idx  = tid + l * 256;
            int krow = idx >> 5;               // 0..15
            int c4   = (idx & 31) * 4;         // 0..124
            float4 vb = *(const float4*)&W[(size_t)(kt + krow) * Nd + colStart + c4];
            *(float4*)&Bs[krow][c4] = vb;
        }
        __syncthreads();

#pragma unroll
        for (int kk = 0; kk < 16; kk++) {
            float ar[8], br[8];
#pragma unroll
            for (int i = 0; i < 8; i++) ar[i] = As[kk][ty * 8 + i];
#pragma unroll
            for (int j = 0; j < 8; j++) br[j] = Bs[kk][tx * 8 + j];
#pragma unroll
            for (int i = 0; i < 8; i++)
#pragma unroll
                for (int j = 0; j < 8; j++)
                    acc[i][j] = fmaf(ar[i], br[j], acc[i][j]);
        }
        __syncthreads();
    }

#pragma unroll
    for (int i = 0; i < 8; i++) {
        int row = rowStart + ty * 8 + i;
#pragma unroll
        for (int j = 0; j < 8; j++) {
            int col = colStart + tx * 8 + j;
            float v = acc[i][j] + bias[col];
            if (EPI == 1)
                v = 0.5f * v * (1.0f + erff(v * 0.70710678118654752f));
            C[(size_t)row * Nd + col] = v;
        }
    }
}

// ---------------------------------------------------------------------------
// Unpack qkvr [8192,3072] -> contiguous q/k/v/r [bh=64][1024][96]
// col = (h*96 + dd)*4 + s
// ---------------------------------------------------------------------------
__global__ void unpack_qkvr(const float* __restrict__ qkvr)
{
    const size_t total = (size_t)MROWS * E4;
    for (size_t idx = (size_t)blockIdx.x * blockDim.x + threadIdx.x;
         idx < total; idx += (size_t)gridDim.x * blockDim.x) {
        int row = (int)(idx / E4);   // b*SEQ + n
        int col = (int)(idx % E4);
        int s  = col & 3;
        int t  = col >> 2;
        int h  = t / HD;
        int dd = t - h * HD;
        int b  = row >> 10;
        int n  = row & 1023;
        size_t dst = ((size_t)(b * HEADS + h) * SEQ + n) * HD + dd;
        float val = qkvr[idx];
        if      (s == 0) g_q[dst] = val;
        else if (s == 1) g_k[dst] = val;
        else if (s == 2) g_v[dst] = val;
        else             g_r[dst] = val;
    }
}

// ---------------------------------------------------------------------------
// energy[bh][i][j] = sum_d Q[bh][i][d] * K[bh][j][d]   (GEMM-NT, K-dim = 96)
// ---------------------------------------------------------------------------
__global__ __launch_bounds__(256) void attn_energy(
    const float* __restrict__ Q, const float* __restrict__ K,
    float* __restrict__ Eout)
{
    __shared__ float As[16][132];
    __shared__ float Bs[16][132];

    const int tid = threadIdx.x;
    const int tx = tid & 15, ty = tid >> 4;
    const int rowStart = blockIdx.y * 128;
    const int colStart = blockIdx.x * 128;
    const int bh = blockIdx.z;

    const float* Qb = Q + (size_t)bh * SEQ * HD;
    const float* Kb = K + (size_t)bh * SEQ * HD;

    float acc[8][8];
#pragma unroll
    for (int i = 0; i < 8; i++)
#pragma unroll
        for (int j = 0; j < 8; j++) acc[i][j] = 0.0f;

    for (int kt = 0; kt < HD; kt += 16) {
#pragma unroll
        for (int l = 0; l < 2; l++) {
            int idx = tid + l * 256;
            int row = idx >> 2;
            int k4  = (idx & 3) * 4;
            float4 va = *(const float4*)&Qb[(size_t)(rowStart + row) * HD + kt + k4];
            As[k4 + 0][row] = va.x; As[k4 + 1][row] = va.y;
            As[k4 + 2][row] = va.z; As[k4 + 3][row] = va.w;
            float4 vb = *(const float4*)&Kb[(size_t)(colStart + row) * HD + kt + k4];
            Bs[k4 + 0][row] = vb.x; Bs[k4 + 1][row] = vb.y;
            Bs[k4 + 2][row] = vb.z; Bs[k4 + 3][row] = vb.w;
        }
        __syncthreads();
#pragma unroll
        for (int kk = 0; kk < 16; kk++) {
            float ar[8], br[8];
#pragma unroll
            for (int i = 0; i < 8; i++) ar[i] = As[kk][ty * 8 + i];
#pragma unroll
            for (int j = 0; j < 8; j++) br[j] = Bs[kk][tx * 8 + j];
#pragma unroll
            for (int i = 0; i < 8; i++)
#pragma unroll
                for (int j = 0; j < 8; j++)
                    acc[i][j] = fmaf(ar[i], br[j], acc[i][j]);
        }
        __syncthreads();
    }

    float* Eb = Eout + (size_t)bh * SEQ * SEQ;
#pragma unroll
    for (int i = 0; i < 8; i++) {
        int row = rowStart + ty * 8 + i;
#pragma unroll
        for (int j = 0; j < 8; j++) {
            int col = colStart + tx * 8 + j;
            Eb[(size_t)row * SEQ + col] = acc[i][j];
        }
    }
}

// ---------------------------------------------------------------------------
// Row softmax of UNSCALED logits, then divide by sqrt(EMB). In place.
// One block (128 threads) per row of 1024.
// ---------------------------------------------------------------------------
__global__ __launch_bounds__(128) void softmax_scale(float* __restrict__ att)
{
    __shared__ float red[128];
    const int tid = threadIdx.x;
    const size_t base = (size_t)blockIdx.x * SEQ;

    float v[8];
    float m = -1e30f;
#pragma unroll
    for (int i = 0; i < 8; i++) {
        v[i] = att[base + tid * 8 + i];
        m = fmaxf(m, v[i]);
    }
    red[tid] = m;
    __syncthreads();
    for (int off = 64; off > 0; off >>= 1) {
        if (tid < off) red[tid] = fmaxf(red[tid], red[tid + off]);
        __syncthreads();
    }
    m = red[0];
    __syncthreads();

    float s = 0.0f;
#pragma unroll
    for (int i = 0; i < 8; i++) {
        v[i] = expf(v[i] - m);
        s += v[i];
    }
    red[tid] = s;
    __syncthreads();
    for (int off = 64; off > 0; off >>= 1) {
        if (tid < off) red[tid] += red[tid + off];
        __syncthreads();
    }
    const float inv = 1.0f / (red[0] * 27.712812921102035f);   // sum * sqrt(768)
#pragma unroll
    for (int i = 0; i < 8; i++)
        att[base + tid * 8 + i] = v[i] * inv;
}

// ---------------------------------------------------------------------------
// out[b][n][h*96+d] = (sum_j att[bh][n][j] * V[bh][j][d]) * R[bh][n][d]
// GEMM-NN, M=1024, N=96, K=1024. 128x96 tile, 8x6 per thread.
// ---------------------------------------------------------------------------
__global__ __launch_bounds__(256) void attn_av(
    const float* __restrict__ att, const float* __restrict__ V,
    const float* __restrict__ R, float* __restrict__ out)
{
    __shared__ float As[16][132];   // att transposed: As[k][m]
    __shared__ float Bs[16][100];   // V: Bs[k][d]

    const int tid = threadIdx.x;
    const int tx = tid & 15, ty = tid >> 4;
    const int rowStart = blockIdx.y * 128;
    const int bh = blockIdx.z;

    const float* Ab = att + (size_t)bh * SEQ * SEQ;
    const float* Vb = V + (size_t)bh * SEQ * HD;

    float acc[8][6];
#pragma unroll
    for (int i = 0; i < 8; i++)
#pragma unroll
        for (int j = 0; j < 6; j++) acc[i][j] = 0.0f;

    for (int kt = 0; kt < SEQ; kt += 16) {
#pragma unroll
        for (int l = 0; l < 2; l++) {
            int idx = tid + l * 256;
            int row = idx >> 2;
            int k4  = (idx & 3) * 4;
            float4 va = *(const float4*)&Ab[(size_t)(rowStart + row) * SEQ + kt + k4];
            As[k4 + 0][row] = va.x; As[k4 + 1][row] = va.y;
            As[k4 + 2][row] = va.z; As[k4 + 3][row] = va.w;
        }
        for (int idx = tid; idx < 384; idx += 256) {     // 16x96 floats = 384 float4
            int krow = idx / 24;
            int c4   = (idx % 24) * 4;
            *(float4*)&Bs[krow][c4] =
                *(const float4*)&Vb[(size_t)(kt + krow) * HD + c4];
        }
        __syncthreads();
#pragma unroll
        for (int kk = 0; kk < 16; kk++) {
            float ar[8], br[6];
#pragma unroll
            for (int i = 0; i < 8; i++) ar[i] = As[kk][ty * 8 + i];
#pragma unroll
            for (int j = 0; j < 6; j++) br[j] = Bs[kk][tx * 6 + j];
#pragma unroll
            for (int i = 0; i < 8; i++)
#pragma unroll
                for (int j = 0; j < 6; j++)
                    acc[i][j] = fmaf(ar[i], br[j], acc[i][j]);
        }
        __syncthreads();
    }

    const int b = bh >> 3;
    const int h = bh & 7;
#pragma unroll
    for (int i = 0; i < 8; i++) {
        int row = rowStart + ty * 8 + i;     // n index
        const float* Rrow = R + (size_t)bh * SEQ * HD + (size_t)row * HD;
        float* Orow = out + ((size_t)(b * SEQ + row)) * EMB + h * HD;
#pragma unroll
        for (int j = 0; j < 6; j++) {
            int d = tx * 6 + j;
            Orow[d] = acc[i][j] * Rrow[d];
        }
    }
}

// ---------------------------------------------------------------------------
// out = LayerNorm(a + b) * g + beta, rows of 768. One block (256 thr) per row.
// ---------------------------------------------------------------------------
__global__ __launch_bounds__(256) void resid_ln(
    const float* __restrict__ a, const float* __restrict__ b,
    const float* __restrict__ g, const float* __restrict__ beta,
    float* __restrict__ out)
{
    __shared__ float red[256];
    const int tid = threadIdx.x;
    const size_t base = (size_t)blockIdx.x * EMB;

    float y[3];
    float s = 0.0f;
#pragma unroll
    for (int i = 0; i < 3; i++) {
        int j = tid + i * 256;
        y[i] = a[base + j] + b[base + j];
        s += y[i];
    }
    red[tid] = s;
    __syncthreads();
    for (int off = 128; off > 0; off >>= 1) {
        if (tid < off) red[tid] += red[tid + off];
        __syncthreads();
    }
    const float mu = red[0] * (1.0f / EMB);
    __syncthreads();

    s = 0.0f;
#pragma unroll
    for (int i = 0; i < 3; i++) {
        float d = y[i] - mu;
        s += d * d;
    }
    red[tid] = s;
    __syncthreads();
    for (int off = 128; off > 0; off >>= 1) {
        if (tid < off) red[tid] += red[tid + off];
        __syncthreads();
    }
    const float inv = rsqrtf(red[0] * (1.0f / EMB) + 1e-5f);
#pragma unroll
    for (int i = 0; i < 3; i++) {
        int j = tid + i * 256;
        out[base + j] = (y[i] - mu) * inv * g[j] + beta[j];
    }
}

// ---------------------------------------------------------------------------
extern "C" void kernel_launch(void* const* d_in, const int* in_sizes, int n_in,
                              void* d_out, int out_size)
{
    (void)in_sizes; (void)n_in; (void)out_size;

    const float* x      = (const float*)d_in[0];
    const float* w_qkvr = (const float*)d_in[1];
    const float* b_qkvr = (const float*)d_in[2];
    const float* w_proj = (const float*)d_in[3];
    const float* b_proj = (const float*)d_in[4];
    const float* ln1_g  = (const float*)d_in[5];
    const float* ln1_b  = (const float*)d_in[6];
    const float* w_ff1  = (const float*)d_in[7];
    const float* b_ff1  = (const float*)d_in[8];
    const float* w_ff2  = (const float*)d_in[9];
    const float* b_ff2  = (const float*)d_in[10];
    const float* ln2_g  = (const float*)d_in[11];
    const float* ln2_b  = (const float*)d_in[12];
    float* out = (float*)d_out;

    float *qkvr, *q, *k, *v, *r, *att, *attout, *proj, *x1, *ffh, *ff;
    cudaGetSymbolAddress((void**)&qkvr,   g_qkvr);
    cudaGetSymbolAddress((void**)&q,      g_q);
    cudaGetSymbolAddress((void**)&k,      g_k);
    cudaGetSymbolAddress((void**)&v,      g_v);
    cudaGetSymbolAddress((void**)&r,      g_r);
    cudaGetSymbolAddress((void**)&att,    g_att);
    cudaGetSymbolAddress((void**)&attout, g_attout);
    cudaGetSymbolAddress((void**)&proj,   g_proj);
    cudaGetSymbolAddress((void**)&x1,     g_x1);
    cudaGetSymbolAddress((void**)&ffh,    g_ffh);
    cudaGetSymbolAddress((void**)&ff,     g_ff);

    // 1. qkvr = x @ w_qkvr + b_qkvr            [8192,3072]
    sgemm_bias<0><<<dim3(E4 / 128, MROWS / 128), 256>>>(
        x, w_qkvr, b_qkvr, qkvr, MROWS, E4, EMB);

    // 2. unpack to contiguous q/k/v/r [64][1024][96]
    unpack_qkvr<<<4096, 256>>>(qkvr);

    // 3. energy = q @ k^T  (unscaled)
    attn_energy<<<dim3(SEQ / 128, SEQ / 128, BH), 256>>>(q, k, att);

    // 4. att = softmax(energy) / sqrt(768)
    softmax_scale<<<BH * SEQ, 128>>>(att);

    // 5. attout = (att @ v) * r, scattered to [b,n,e]
    attn_av<<<dim3(1, SEQ / 128, BH), 256>>>(att, v, r, attout);

    // 6. proj = attout @ w_proj + b_proj
    sgemm_bias<0><<<dim3(EMB / 128, MROWS / 128), 256>>>(
        attout, w_proj, b_proj, proj, MROWS, EMB, EMB);

    // 7. x1 = LN(proj + x)
    resid_ln<<<MROWS, 256>>>(proj, x, ln1_g, ln1_b, x1);

    // 8. ffh = gelu(x1 @ w_ff1 + b_ff1)
    sgemm_bias<1><<<dim3(E4 / 128, MROWS / 128), 256>>>(
        x1, w_ff1, b_ff1, ffh, MROWS, E4, EMB);

    // 9. ff = ffh @ w_ff2 + b_ff2
    sgemm_bias<0><<<dim3(EMB / 128, MROWS / 128), 256>>>(
        ffh, w_ff2, b_ff2, ff, MROWS, EMB, E4);

    // 10. out = LN(ff + x1)
    resid_ln<<<MROWS, 256>>>(ff, x1, ln2_g, ln2_b, out);
}

// round 5
// speedup vs baseline: 1.4854x; 1.4854x over previous
#include <cuda_runtime.h>
#include <mma.h>
#include <math.h>

using namespace nvcuda;

// ---------------------------------------------------------------------------
// EncoderBlock: B=8, N=1024, E=768, H=8, d=96  — tf32 tensor-core version
// ---------------------------------------------------------------------------

#define Bb    8
#define SEQ   1024
#define EMB   768
#define HEADS 8
#define HD    96
#define MROWS (Bb * SEQ)     // 8192
#define E4    (4 * EMB)      // 3072
#define BH    (Bb * HEADS)   // 64

// Scratch (static device globals)
__device__ float g_qkvr  [(size_t)MROWS * E4];   // also reused as AV-raw scratch
__device__ float g_q     [(size_t)BH * SEQ * HD];
__device__ float g_k     [(size_t)BH * SEQ * HD];
__device__ float g_v     [(size_t)BH * SEQ * HD];
__device__ float g_r     [(size_t)BH * SEQ * HD];
__device__ float g_att   [(size_t)BH * SEQ * SEQ];
__device__ float g_attout[(size_t)MROWS * EMB];
__device__ float g_proj  [(size_t)MROWS * EMB];
__device__ float g_x1    [(size_t)MROWS * EMB];
__device__ float g_ffh   [(size_t)MROWS * E4];
__device__ float g_ff    [(size_t)MROWS * EMB];

// ---------------------------------------------------------------------------
// tf32 GEMM: C[M,N] = A[M,K] @ W[K,N]  (raw product; bias folded downstream)
// 128x128 block tile, BK=32, 256 threads (8 warps), warp tile 32x64.
// Requires M%128==0, N%128==0, K%32==0 (all call sites satisfy).
// ---------------------------------------------------------------------------
__global__ __launch_bounds__(256) void gemm_tf32(
    const float* __restrict__ A, const float* __restrict__ W,
    float* __restrict__ C, int Md, int Nd, int Kd)
{
    __shared__ float As[128][40];   // row-major A tile (tf32-rounded)
    __shared__ float Bs[32][136];   // row-major W tile (tf32-rounded)

    const int tid = threadIdx.x;
    const int warpId = tid >> 5;
    const int warpM = warpId >> 1;      // 0..3  -> 32 rows
    const int warpN = warpId & 1;       // 0..1  -> 64 cols
    const int rowStart = blockIdx.y * 128;
    const int colStart = blockIdx.x * 128;

    wmma::fragment<wmma::accumulator, 16, 16, 8, float> acc[2][4];
#pragma unroll
    for (int i = 0; i < 2; i++)
#pragma unroll
        for (int j = 0; j < 4; j++) wmma::fill_fragment(acc[i][j], 0.0f);

    for (int kt = 0; kt < Kd; kt += 32) {
        // A tile 128x32 -> 1024 float4, 4 per thread
#pragma unroll
        for (int l = 0; l < 4; l++) {
            int idx = tid + l * 256;
            int row = idx >> 3;
            int k4  = (idx & 7) * 4;
            float4 v = *(const float4*)&A[(size_t)(rowStart + row) * Kd + kt + k4];
            As[row][k4 + 0] = wmma::__float_to_tf32(v.x);
            As[row][k4 + 1] = wmma::__float_to_tf32(v.y);
            As[row][k4 + 2] = wmma::__float_to_tf32(v.z);
            As[row][k4 + 3] = wmma::__float_to_tf32(v.w);
        }
        // W tile 32x128 -> 1024 float4, 4 per thread
#pragma unroll
        for (int l = 0; l < 4; l++) {
            int idx = tid + l * 256;
            int kr = idx >> 5;
            int c4 = (idx & 31) * 4;
            float4 v = *(const float4*)&W[(size_t)(kt + kr) * Nd + colStart + c4];
            Bs[kr][c4 + 0] = wmma::__float_to_tf32(v.x);
            Bs[kr][c4 + 1] = wmma::__float_to_tf32(v.y);
            Bs[kr][c4 + 2] = wmma::__float_to_tf32(v.z);
            Bs[kr][c4 + 3] = wmma::__float_to_tf32(v.w);
        }
        __syncthreads();

#pragma unroll
        for (int kk = 0; kk < 32; kk += 8) {
            wmma::fragment<wmma::matrix_a, 16, 16, 8, wmma::precision::tf32, wmma::row_major> af[2];
            wmma::fragment<wmma::matrix_b, 16, 16, 8, wmma::precision::tf32, wmma::row_major> bf[4];
#pragma unroll
            for (int i = 0; i < 2; i++)
                wmma::load_matrix_sync(af[i], &As[warpM * 32 + i * 16][kk], 40);
#pragma unroll
            for (int j = 0; j < 4; j++)
                wmma::load_matrix_sync(bf[j], &Bs[kk][warpN * 64 + j * 16], 136);
#pragma unroll
            for (int i = 0; i < 2; i++)
#pragma unroll
                for (int j = 0; j < 4; j++)
                    wmma::mma_sync(acc[i][j], af[i], bf[j], acc[i][j]);
        }
        __syncthreads();
    }

#pragma unroll
    for (int i = 0; i < 2; i++)
#pragma unroll
        for (int j = 0; j < 4; j++)
            wmma::store_matrix_sync(
                &C[(size_t)(rowStart + warpM * 32 + i * 16) * Nd +
                   colStart + warpN * 64 + j * 16],
                acc[i][j], Nd, wmma::mem_row_major);
}

// ---------------------------------------------------------------------------
// energy[bh][i][j] = Q[bh][i][:] . K[bh][j][:]   (GEMM-NT, K-dim = 96, tf32)
// ---------------------------------------------------------------------------
__global__ __launch_bounds__(256) void attn_energy_tf32(
    const float* __restrict__ Q, const float* __restrict__ K,
    float* __restrict__ Eout)
{
    __shared__ float As[128][40];   // Q rows
    __shared__ float Ks[128][40];   // K rows (used col-major by matrix_b)

    const int tid = threadIdx.x;
    const int warpId = tid >> 5;
    const int warpM = warpId >> 1;
    const int warpN = warpId & 1;
    const int rowStart = blockIdx.y * 128;
    const int colStart = blockIdx.x * 128;
    const int bh = blockIdx.z;

    const float* Qb = Q + (size_t)bh * SEQ * HD;
    const float* Kb = K + (size_t)bh * SEQ * HD;

    wmma::fragment<wmma::accumulator, 16, 16, 8, float> acc[2][4];
#pragma unroll
    for (int i = 0; i < 2; i++)
#pragma unroll
        for (int j = 0; j < 4; j++) wmma::fill_fragment(acc[i][j], 0.0f);

    for (int kt = 0; kt < HD; kt += 32) {
#pragma unroll
        for (int l = 0; l < 4; l++) {
            int idx = tid + l * 256;
            int row = idx >> 3;
            int k4  = (idx & 7) * 4;
            float4 va = *(const float4*)&Qb[(size_t)(rowStart + row) * HD + kt + k4];
            As[row][k4 + 0] = wmma::__float_to_tf32(va.x);
            As[row][k4 + 1] = wmma::__float_to_tf32(va.y);
            As[row][k4 + 2] = wmma::__float_to_tf32(va.z);
            As[row][k4 + 3] = wmma::__float_to_tf32(va.w);
            float4 vb = *(const float4*)&Kb[(size_t)(colStart + row) * HD + kt + k4];
            Ks[row][k4 + 0] = wmma::__float_to_tf32(vb.x);
            Ks[row][k4 + 1] = wmma::__float_to_tf32(vb.y);
            Ks[row][k4 + 2] = wmma::__float_to_tf32(vb.z);
            Ks[row][k4 + 3] = wmma::__float_to_tf32(vb.w);
        }
        __syncthreads();

#pragma unroll
        for (int kk = 0; kk < 32; kk += 8) {
            wmma::fragment<wmma::matrix_a, 16, 16, 8, wmma::precision::tf32, wmma::row_major> af[2];
            wmma::fragment<wmma::matrix_b, 16, 16, 8, wmma::precision::tf32, wmma::col_major> bf[4];
#pragma unroll
            for (int i = 0; i < 2; i++)
                wmma::load_matrix_sync(af[i], &As[warpM * 32 + i * 16][kk], 40);
#pragma unroll
            for (int j = 0; j < 4; j++)
                wmma::load_matrix_sync(bf[j], &Ks[warpN * 64 + j * 16][kk], 40);
#pragma unroll
            for (int i = 0; i < 2; i++)
#pragma unroll
                for (int j = 0; j < 4; j++)
                    wmma::mma_sync(acc[i][j], af[i], bf[j], acc[i][j]);
        }
        __syncthreads();
    }

    float* Eb = Eout + (size_t)bh * SEQ * SEQ;
#pragma unroll
    for (int i = 0; i < 2; i++)
#pragma unroll
        for (int j = 0; j < 4; j++)
            wmma::store_matrix_sync(
                &Eb[(size_t)(rowStart + warpM * 32 + i * 16) * SEQ +
                    colStart + warpN * 64 + j * 16],
                acc[i][j], SEQ, wmma::mem_row_major);
}

// ---------------------------------------------------------------------------
// avraw[bh][n][d] = att[bh][n][:] @ V[bh][:][d]   (M=1024, N=96, K=1024, tf32)
// 128x96 tile, warp tile 32x48.
// ---------------------------------------------------------------------------
__global__ __launch_bounds__(256) void attn_av_tf32(
    const float* __restrict__ att, const float* __restrict__ V,
    float* __restrict__ avraw)
{
    __shared__ float As[128][40];
    __shared__ float Bs[32][104];

    const int tid = threadIdx.x;
    const int warpId = tid >> 5;
    const int warpM = warpId >> 1;      // 0..3
    const int warpN = warpId & 1;       // 0..1 -> 48 cols each
    const int rowStart = blockIdx.y * 128;
    const int bh = blockIdx.z;

    const float* Ab = att + (size_t)bh * SEQ * SEQ;
    const float* Vb = V + (size_t)bh * SEQ * HD;

    wmma::fragment<wmma::accumulator, 16, 16, 8, float> acc[2][3];
#pragma unroll
    for (int i = 0; i < 2; i++)
#pragma unroll
        for (int j = 0; j < 3; j++) wmma::fill_fragment(acc[i][j], 0.0f);

    for (int kt = 0; kt < SEQ; kt += 32) {
#pragma unroll
        for (int l = 0; l < 4; l++) {
            int idx = tid + l * 256;
            int row = idx >> 3;
            int k4  = (idx & 7) * 4;
            float4 va = *(const float4*)&Ab[(size_t)(rowStart + row) * SEQ + kt + k4];
            As[row][k4 + 0] = wmma::__float_to_tf32(va.x);
            As[row][k4 + 1] = wmma::__float_to_tf32(va.y);
            As[row][k4 + 2] = wmma::__float_to_tf32(va.z);
            As[row][k4 + 3] = wmma::__float_to_tf32(va.w);
        }
        // V tile 32x96 = 768 float4, 3 per thread
#pragma unroll
        for (int l = 0; l < 3; l++) {
            int idx = tid + l * 256;
            int kr = idx / 24;
            int c4 = (idx % 24) * 4;
            float4 vb = *(const float4*)&Vb[(size_t)(kt + kr) * HD + c4];
            Bs[kr][c4 + 0] = wmma::__float_to_tf32(vb.x);
            Bs[kr][c4 + 1] = wmma::__float_to_tf32(vb.y);
            Bs[kr][c4 + 2] = wmma::__float_to_tf32(vb.z);
            Bs[kr][c4 + 3] = wmma::__float_to_tf32(vb.w);
        }
        __syncthreads();

#pragma unroll
        for (int kk = 0; kk < 32; kk += 8) {
            wmma::fragment<wmma::matrix_a, 16, 16, 8, wmma::precision::tf32, wmma::row_major> af[2];
            wmma::fragment<wmma::matrix_b, 16, 16, 8, wmma::precision::tf32, wmma::row_major> bf[3];
#pragma unroll
            for (int i = 0; i < 2; i++)
                wmma::load_matrix_sync(af[i], &As[warpM * 32 + i * 16][kk], 40);
#pragma unroll
            for (int j = 0; j < 3; j++)
                wmma::load_matrix_sync(bf[j], &Bs[kk][warpN * 48 + j * 16], 104);
#pragma unroll
            for (int i = 0; i < 2; i++)
#pragma unroll
                for (int j = 0; j < 3; j++)
                    wmma::mma_sync(acc[i][j], af[i], bf[j], acc[i][j]);
        }
        __syncthreads();
    }

    float* Sb = avraw + (size_t)bh * SEQ * HD;
#pragma unroll
    for (int i = 0; i < 2; i++)
#pragma unroll
        for (int j = 0; j < 3; j++)
            wmma::store_matrix_sync(
                &Sb[(size_t)(rowStart + warpM * 32 + i * 16) * HD +
                    warpN * 48 + j * 16],
                acc[i][j], HD, wmma::mem_row_major);
}

// ---------------------------------------------------------------------------
// Unpack qkvr raw [8192,3072] (+bias) -> q/k/v/r [bh=64][1024][96]
// col = (h*96 + dd)*4 + s
// ---------------------------------------------------------------------------
__global__ void unpack_qkvr(const float* __restrict__ qkvr,
                            const float* __restrict__ bias)
{
    const size_t total = (size_t)MROWS * E4;
    for (size_t idx = (size_t)blockIdx.x * blockDim.x + threadIdx.x;
         idx < total; idx += (size_t)gridDim.x * blockDim.x) {
        int row = (int)(idx / E4);
        int col = (int)(idx % E4);
        int s  = col & 3;
        int t  = col >> 2;
        int h  = t / HD;
        int dd = t - h * HD;
        int b  = row >> 10;
        int n  = row & 1023;
        size_t dst = ((size_t)(b * HEADS + h) * SEQ + n) * HD + dd;
        float val = qkvr[idx] + bias[col];
        if      (s == 0) g_q[dst] = val;
        else if (s == 1) g_k[dst] = val;
        else if (s == 2) g_v[dst] = val;
        else             g_r[dst] = val;
    }
}

// ---------------------------------------------------------------------------
// Row softmax of UNSCALED logits, then /sqrt(EMB). Coalesced float4 access.
// 128 threads per 1024-row.
// ---------------------------------------------------------------------------
__global__ __launch_bounds__(128) void softmax_scale(float* __restrict__ att)
{
    __shared__ float red[128];
    const int tid = threadIdx.x;
    float4* rowp = (float4*)(att + (size_t)blockIdx.x * SEQ);

    float4 a = rowp[tid];
    float4 b = rowp[tid + 128];
    float m = fmaxf(fmaxf(fmaxf(a.x, a.y), fmaxf(a.z, a.w)),
                    fmaxf(fmaxf(b.x, b.y), fmaxf(b.z, b.w)));
    red[tid] = m;
    __syncthreads();
    for (int off = 64; off > 0; off >>= 1) {
        if (tid < off) red[tid] = fmaxf(red[tid], red[tid + off]);
        __syncthreads();
    }
    m = red[0];
    __syncthreads();

    a.x = expf(a.x - m); a.y = expf(a.y - m); a.z = expf(a.z - m); a.w = expf(a.w - m);
    b.x = expf(b.x - m); b.y = expf(b.y - m); b.z = expf(b.z - m); b.w = expf(b.w - m);
    float s = a.x + a.y + a.z + a.w + b.x + b.y + b.z + b.w;
    red[tid] = s;
    __syncthreads();
    for (int off = 64; off > 0; off >>= 1) {
        if (tid < off) red[tid] += red[tid + off];
        __syncthreads();
    }
    const float inv = 1.0f / (red[0] * 27.712812921102035f);   // sum * sqrt(768)
    a.x *= inv; a.y *= inv; a.z *= inv; a.w *= inv;
    b.x *= inv; b.y *= inv; b.z *= inv; b.w *= inv;
    rowp[tid] = a;
    rowp[tid + 128] = b;
}

// ---------------------------------------------------------------------------
// r-gate + head merge: attout[b,n,h*96+d] = avraw[bh][n][d] * r[bh][n][d]
// ---------------------------------------------------------------------------
__global__ __launch_bounds__(256) void rgate_merge(
    const float* __restrict__ avraw, const float* __restrict__ R,
    float* __restrict__ out)
{
    const size_t total4 = (size_t)MROWS * EMB / 4;   // 1.57M float4
    for (size_t idx = (size_t)blockIdx.x * blockDim.x + threadIdx.x;
         idx < total4; idx += (size_t)gridDim.x * blockDim.x) {
        int row = (int)(idx / 192);        // 768/4 float4 per row
        int c4  = (int)(idx % 192);
        int col = c4 * 4;
        int h  = col / HD;
        int d  = col - h * HD;
        int b  = row >> 10;
        int n  = row & 1023;
        size_t src = (((size_t)(b * HEADS + h) * SEQ + n) * HD + d) / 4;
        float4 p = ((const float4*)avraw)[src];
        float4 g = ((const float4*)R)[src];
        p.x *= g.x; p.y *= g.y; p.z *= g.z; p.w *= g.w;
        ((float4*)out)[idx] = p;
    }
}

// ---------------------------------------------------------------------------
// ffh = gelu(ffh + b_ff1), exact erf GELU, vectorized
// ---------------------------------------------------------------------------
__global__ __launch_bounds__(256) void bias_gelu(
    float* __restrict__ ffh, const float* __restrict__ bias)
{
    const size_t total4 = (size_t)MROWS * E4 / 4;
    for (size_t idx = (size_t)blockIdx.x * blockDim.x + threadIdx.x;
         idx < total4; idx += (size_t)gridDim.x * blockDim.x) {
        int c4 = (int)(idx % (E4 / 4));
        float4 bv = ((const float4*)bias)[c4];
        float4 v = ((float4*)ffh)[idx];
        v.x += bv.x; v.y += bv.y; v.z += bv.z; v.w += bv.w;
        v.x = 0.5f * v.x * (1.0f + erff(v.x * 0.70710678118654752f));
        v.y = 0.5f * v.y * (1.0f + erff(v.y * 0.70710678118654752f));
        v.z = 0.5f * v.z * (1.0f + erff(v.z * 0.70710678118654752f));
        v.w = 0.5f * v.w * (1.0f + erff(v.w * 0.70710678118654752f));
        ((float4*)ffh)[idx] = v;
    }
}

// ---------------------------------------------------------------------------
// out = LayerNorm(a + bias2 + b) * g + beta, rows of 768.
// ---------------------------------------------------------------------------
__global__ __launch_bounds__(256) void resid_ln_bias(
    const float* __restrict__ a, const float* __restrict__ bias2,
    const float* __restrict__ b,
    const float* __restrict__ g, const float* __restrict__ beta,
    float* __restrict__ out)
{
    __shared__ float red[256];
    const int tid = threadIdx.x;
    const size_t base = (size_t)blockIdx.x * EMB;

    float y[3];
    float s = 0.0f;
#pragma unroll
    for (int i = 0; i < 3; i++) {
        int j = tid + i * 256;
        y[i] = a[base + j] + bias2[j] + b[base + j];
        s += y[i];
    }
    red[tid] = s;
    __syncthreads();
    for (int off = 128; off > 0; off >>= 1) {
        if (tid < off) red[tid] += red[tid + off];
        __syncthreads();
    }
    const float mu = red[0] * (1.0f / EMB);
    __syncthreads();

    s = 0.0f;
#pragma unroll
    for (int i = 0; i < 3; i++) {
        float d = y[i] - mu;
        s += d * d;
    }
    red[tid] = s;
    __syncthreads();
    for (int off = 128; off > 0; off >>= 1) {
        if (tid < off) red[tid] += red[tid + off];
        __syncthreads();
    }
    const float inv = rsqrtf(red[0] * (1.0f / EMB) + 1e-5f);
#pragma unroll
    for (int i = 0; i < 3; i++) {
        int j = tid + i * 256;
        out[base + j] = (y[i] - mu) * inv * g[j] + beta[j];
    }
}

// ---------------------------------------------------------------------------
extern "C" void kernel_launch(void* const* d_in, const int* in_sizes, int n_in,
                              void* d_out, int out_size)
{
    (void)in_sizes; (void)n_in; (void)out_size;

    const float* x      = (const float*)d_in[0];
    const float* w_qkvr = (const float*)d_in[1];
    const float* b_qkvr = (const float*)d_in[2];
    const float* w_proj = (const float*)d_in[3];
    const float* b_proj = (const float*)d_in[4];
    const float* ln1_g  = (const float*)d_in[5];
    const float* ln1_b  = (const float*)d_in[6];
    const float* w_ff1  = (const float*)d_in[7];
    const float* b_ff1  = (const float*)d_in[8];
    const float* w_ff2  = (const float*)d_in[9];
    const float* b_ff2  = (const float*)d_in[10];
    const float* ln2_g  = (const float*)d_in[11];
    const float* ln2_b  = (const float*)d_in[12];
    float* out = (float*)d_out;

    float *qkvr, *q, *k, *v, *r, *att, *attout, *proj, *x1, *ffh, *ff;
    cudaGetSymbolAddress((void**)&qkvr,   g_qkvr);
    cudaGetSymbolAddress((void**)&q,      g_q);
    cudaGetSymbolAddress((void**)&k,      g_k);
    cudaGetSymbolAddress((void**)&v,      g_v);
    cudaGetSymbolAddress((void**)&r,      g_r);
    cudaGetSymbolAddress((void**)&att,    g_att);
    cudaGetSymbolAddress((void**)&attout, g_attout);
    cudaGetSymbolAddress((void**)&proj,   g_proj);
    cudaGetSymbolAddress((void**)&x1,     g_x1);
    cudaGetSymbolAddress((void**)&ffh,    g_ffh);
    cudaGetSymbolAddress((void**)&ff,     g_ff);

    // 1. qkvr = x @ w_qkvr (raw)
    gemm_tf32<<<dim3(E4 / 128, MROWS / 128), 256>>>(x, w_qkvr, qkvr, MROWS, E4, EMB);

    // 2. unpack (+ b_qkvr) -> q/k/v/r [64][1024][96]
    unpack_qkvr<<<4096, 256>>>(qkvr, b_qkvr);

    // 3. energy = q @ k^T (unscaled)
    attn_energy_tf32<<<dim3(SEQ / 128, SEQ / 128, BH), 256>>>(q, k, att);

    // 4. softmax / sqrt(768)
    softmax_scale<<<BH * SEQ, 128>>>(att);

    // 5. avraw = att @ v   (reuse g_qkvr as scratch)
    attn_av_tf32<<<dim3(1, SEQ / 128, BH), 256>>>(att, v, qkvr);

    // 6. attout = avraw * r, merged to [b,n,e]
    rgate_merge<<<2048, 256>>>(qkvr, r, attout);

    // 7. proj = attout @ w_proj (raw)
    gemm_tf32<<<dim3(EMB / 128, MROWS / 128), 256>>>(attout, w_proj, proj, MROWS, EMB, EMB);

    // 8. x1 = LN(proj + b_proj + x)
    resid_ln_bias<<<MROWS, 256>>>(proj, b_proj, x, ln1_g, ln1_b, x1);

    // 9. ffh = x1 @ w_ff1 (raw)
    gemm_tf32<<<dim3(E4 / 128, MROWS / 128), 256>>>(x1, w_ff1, ffh, MROWS, E4, EMB);

    // 10. ffh = gelu(ffh + b_ff1)
    bias_gelu<<<8192, 256>>>(ffh, b_ff1);

    // 11. ff = ffh @ w_ff2 (raw)
    gemm_tf32<<<dim3(EMB / 128, MROWS / 128), 256>>>(ffh, w_ff2, ff, MROWS, EMB, E4);

    // 12. out = LN(ff + b_ff2 + x1)
    resid_ln_bias<<<MROWS, 256>>>(ff, b_ff2, x1, ln2_g, ln2_b, out);
}